// round 14
// baseline (speedup 1.0000x reference)
#include <cuda_runtime.h>
#include <stdint.h>

#define N 96
#define D 64
#define C 21
#define MARGIN_F 0.3f
#define ONE_F_BITS 0x3F800000u

#define TJ 8
#define TK 8
#define NZPAIR 66               // #(jt,kt) with jt>kt
#define NWPAIR 78               // #(jt,kt) with jt<=kt

#define NBLK_PREP  N                      // 96
#define NBLK_ZERO  (NZPAIR * N)           // 6336
#define NBLK_WORK  (NWPAIR * N)           // 7488
#define ZERO_BASE  NBLK_PREP              // 96
#define WORK_BASE  (NBLK_PREP + NBLK_ZERO) // 6432
#define NBLK_TOTAL (WORK_BASE + NBLK_WORK) // 13920

// Scratch (no allocations allowed in kernel_launch)
__device__ unsigned char  g_sames[N * N];
// B[i,p,n] float-encoded (0x0 / 0x3F800000), 24 uint4 per (i,p). 3.4 MB, L2-resident.
__device__ uint4          g_B4[N * N * 24];
// prep-done flag + self-cleaning counter (both return to 0 at end of each call)
__device__ int            g_flag;
__device__ int            g_done;

// tile-pair lookup tables (literal -> zero decode cost)
__constant__ uint8_t ZJT[NZPAIR] = {
    1,
    2,2,
    3,3,3,
    4,4,4,4,
    5,5,5,5,5,
    6,6,6,6,6,6,
    7,7,7,7,7,7,7,
    8,8,8,8,8,8,8,8,
    9,9,9,9,9,9,9,9,9,
    10,10,10,10,10,10,10,10,10,10,
    11,11,11,11,11,11,11,11,11,11,11 };
__constant__ uint8_t ZKT[NZPAIR] = {
    0,
    0,1,
    0,1,2,
    0,1,2,3,
    0,1,2,3,4,
    0,1,2,3,4,5,
    0,1,2,3,4,5,6,
    0,1,2,3,4,5,6,7,
    0,1,2,3,4,5,6,7,8,
    0,1,2,3,4,5,6,7,8,9,
    0,1,2,3,4,5,6,7,8,9,10 };
__constant__ uint8_t WJT[NWPAIR] = {
    0,0,0,0,0,0,0,0,0,0,0,0,
    1,1,1,1,1,1,1,1,1,1,1,
    2,2,2,2,2,2,2,2,2,2,
    3,3,3,3,3,3,3,3,3,
    4,4,4,4,4,4,4,4,
    5,5,5,5,5,5,5,
    6,6,6,6,6,6,
    7,7,7,7,7,
    8,8,8,8,
    9,9,9,
    10,10,
    11 };
__constant__ uint8_t WKT[NWPAIR] = {
    0,1,2,3,4,5,6,7,8,9,10,11,
    1,2,3,4,5,6,7,8,9,10,11,
    2,3,4,5,6,7,8,9,10,11,
    3,4,5,6,7,8,9,10,11,
    4,5,6,7,8,9,10,11,
    5,6,7,8,9,10,11,
    6,7,8,9,10,11,
    7,8,9,10,11,
    8,9,10,11,
    9,10,11,
    10,11,
    11 };

// ---------------------------------------------------------------------------
// ONE kernel, roles by bid range. Prep->work dependency enforced by an
// explicit flag (96 prep arrivals), NOT by scheduling luck. Deadlock-free:
// all 96 prep blocks are dispatched in wave 1 (n_conc ~ 1184 blocks),
// strictly before any work block (bid >= 6432) becomes resident.
// launch_bounds(256, 8): 8 blocks/SM for store-latency coverage.
// ---------------------------------------------------------------------------
__global__ __launch_bounds__(256, 8)
void miner_kernel(const float* __restrict__ logits,
                  const float* __restrict__ labels,
                  const float* __restrict__ feat2,
                  uint4* __restrict__ out) {
    const int bid = blockIdx.x;
    const int t   = threadIdx.x;

    // ======================= role 1: prep (bids 0..95) =====================
    if (bid < NBLK_PREP) {
        const int i = bid;
        const int j = t;

        __shared__ float         xs[D];
        __shared__ float         li[C];
        __shared__ float         inv_nx;
        __shared__ float         mrow[N];
        __shared__ unsigned char drow[N];

        if (j < D) xs[j] = logits[i * D + j];
        if (j < C) li[j] = labels[i * C + j];
        __syncthreads();

        if (j == 0) {
            float s = 0.f;
            #pragma unroll
            for (int c = 0; c < D; c++) s += xs[c] * xs[c];
            inv_nx = 1.0f / fmaxf(sqrtf(s), 1e-12f);
        }
        __syncthreads();

        if (j < N) {
            float dot = 0.f, nyy = 0.f;
            #pragma unroll
            for (int c = 0; c < D; c++) {
                float y = feat2[j * D + c];
                dot += xs[c] * y;
                nyy += y * y;
            }
            const float inv_ny = 1.0f / fmaxf(sqrtf(nyy), 1e-12f);
            mrow[j] = -(dot * inv_nx * inv_ny);

            float ld = 0.f;
            #pragma unroll
            for (int c = 0; c < C; c++) ld += li[c] * labels[j * C + c];
            const bool share = (ld > 0.0f);
            g_sames[i * N + j] = (share && (i != j)) ? 1 : 0;
            drow[j] = share ? 0 : 1;         // diagonal NOT filled (matches ref)
        }
        __syncthreads();

        if (j < N) {
            const float mp = mrow[j];
            uint4* dst = &g_B4[(i * N + j) * 24];
            #pragma unroll
            for (int v = 0; v < 24; v++) {
                uint4 w;
                w.x = (drow[4*v+0] && (mrow[4*v+0] - mp <= MARGIN_F)) ? ONE_F_BITS : 0u;
                w.y = (drow[4*v+1] && (mrow[4*v+1] - mp <= MARGIN_F)) ? ONE_F_BITS : 0u;
                w.z = (drow[4*v+2] && (mrow[4*v+2] - mp <= MARGIN_F)) ? ONE_F_BITS : 0u;
                w.w = (drow[4*v+3] && (mrow[4*v+3] - mp <= MARGIN_F)) ? ONE_F_BITS : 0u;
                dst[v] = w;
            }
        }

        // signal: this i-slab of g_B4 / g_sames is globally visible
        __syncthreads();
        if (t == 0) {
            __threadfence();
            atomicAdd(&g_flag, 1);
        }
        return;
    }

    const int jj   = t >> 5;                // warp -> output j-row in tile
    const int lane = t & 31;

    // ================= role 2: zero-fill (bids 96..6431) ===================
    if (bid < WORK_BASE) {
        const int z  = bid - ZERO_BASE;
        const int i  = z / NZPAIR;
        const int p  = z - i * NZPAIR;
        const int j0 = (int)ZJT[p] * TJ;
        const int k0 = (int)ZKT[p] * TK;

        uint4* __restrict__ orow =
            out + ((size_t)((i * N + j0 + jj) * N + k0)) * 24;
        const uint4 zv = make_uint4(0u, 0u, 0u, 0u);
        #pragma unroll
        for (int it = 0; it < 6; it++)
            orow[it * 32 + lane] = zv;
        return;
    }

    // ================= role 3: work-fill (bids 6432..13919) ================
    {
        // wait for all 96 prep blocks (normally already done -> one atomic)
        if (t == 0) {
            while (atomicAdd(&g_flag, 0) < NBLK_PREP) __nanosleep(128);
        }
        __syncthreads();

        const int w  = bid - WORK_BASE;
        const int i  = w / NWPAIR;
        const int q  = w - i * NWPAIR;
        const int jt = (int)WJT[q];
        const int kt = (int)WKT[q];
        const int j0 = jt * TJ;
        const int k0 = kt * TK;

        __shared__ uint4         sBj[TJ][24];
        __shared__ uint4         sBk[TK][24];
        __shared__ unsigned char ssj[TJ];
        __shared__ unsigned char ssk[TK];

        // load 384 uint4 (rows 0-7 -> sBj, 8-15 -> sBk)
        {
            int l = t;
            {
                const int row = l / 24, v = l % 24;
                const int src_p = (row < TJ) ? (j0 + row) : (k0 + row - TJ);
                uint4 val = g_B4[(i * N + src_p) * 24 + v];
                if (row < TJ) sBj[row][v] = val; else sBk[row - TJ][v] = val;
            }
            l = t + 256;
            if (l < 384) {
                const int row = l / 24, v = l % 24;
                const int src_p = (row < TJ) ? (j0 + row) : (k0 + row - TJ);
                uint4 val = g_B4[(i * N + src_p) * 24 + v];
                if (row < TJ) sBj[row][v] = val; else sBk[row - TJ][v] = val;
            }
            if (t < TJ)            ssj[t] = g_sames[i * N + j0 + t];
            else if (t < TJ + TK)  ssk[t - TJ] = g_sames[i * N + k0 + (t - TJ)];
        }
        __syncthreads();

        const bool diag = (jt == kt);
        const uint4 z = make_uint4(0u, 0u, 0u, 0u);

        uint4* __restrict__ orow =
            out + ((size_t)((i * N + j0 + jj) * N + k0)) * 24;
        const uint4* aRow = sBj[jj];
        const bool   sj   = ssj[jj] != 0;

        #pragma unroll
        for (int it = 0; it < 6; it++) {
            const int idx = it * 32 + lane;          // 0..191
            const int kk  = idx / 24;                // const-div (mul-shift)
            const int v   = idx - kk * 24;

            const bool valid = sj && ssk[kk] && (!diag || jj < kk);
            uint4 res = z;
            if (valid) {
                const uint4 a = aRow[v];
                const uint4 b = sBk[kk][v];
                res = make_uint4(a.x | b.x, a.y | b.y, a.z | b.z, a.w | b.w);
            }
            orow[idx] = res;
        }

        // self-clean: last work block resets flags (next call starts at 0)
        if (t == 0) {
            const int d = atomicAdd(&g_done, 1);
            if (d == NBLK_WORK - 1) {
                atomicExch(&g_flag, 0);
                atomicExch(&g_done, 0);
            }
        }
    }
}

// ---------------------------------------------------------------------------
extern "C" void kernel_launch(void* const* d_in, const int* in_sizes, int n_in,
                              void* d_out, int out_size) {
    const float* logits = (const float*)d_in[0];   // [96, 64]
    const float* labels = (const float*)d_in[1];   // [96, 21]
    const float* feat2  = (const float*)d_in[2];   // [96, 64]

    miner_kernel<<<NBLK_TOTAL, 256>>>(logits, labels, feat2, (uint4*)d_out);
}